// round 1
// baseline (speedup 1.0000x reference)
#include <cuda_runtime.h>
#include <math.h>

#define NSAMP 24000
#define NTHR  1024
#define CHUNK ((NSAMP + NTHR - 1) / NTHR)   // 24
#define CUTOFF 0.1f

__global__ __launch_bounds__(NTHR, 1)
void drum_synth_kernel(const float* __restrict__ p,
                       const float* __restrict__ noise_t,
                       const float* __restrict__ noise_n,
                       float* __restrict__ out)
{
    extern __shared__ float smem[];
    float* trans = smem;            // NSAMP floats
    float* res   = smem + NSAMP;    // NSAMP floats
    __shared__ float sA[NTHR];
    __shared__ float sB[NTHR];

    const int tid = threadIdx.x;

    // Zero-init resonator buffer (reference scans over a zero-initialized array;
    // needed for the generic path's speculative reads).
    for (int i = tid; i < NSAMP; i += NTHR) res[i] = 0.0f;

    // ---- parameters (broadcast reads) ----
    const float decay_t  = p[1];
    const float freq_t   = p[2];
    const float sat      = p[3];
    const float gain_t   = p[4];
    const float freq_r   = p[5];
    const float feedback = p[6];
    const float gain_r   = p[7];
    const float attack_n = p[8];
    const float decay_n  = p[9];
    const float gain_n   = p[10];

    const float tstep = 1.0f / (float)(NSAMP - 1);

    // ======== Phase 1: one-pole filter as affine-map scan ========
    // pass 1: per-chunk transform y -> A*y + B  (starting from y=0 gives B)
    {
        const int start = tid * CHUNK;
        const int end   = min(start + CHUNK, NSAMP);
        float a = 1.0f, b = 0.0f;
        for (int k = start; k < end; ++k) {
            float x = noise_t[k];
            b = CUTOFF * x + (1.0f - CUTOFF) * b;
            a *= (1.0f - CUTOFF);
        }
        sA[tid] = a;
        sB[tid] = b;
    }
    __syncthreads();

    // Hillis-Steele inclusive scan of affine maps: (A2,B2)∘(A1,B1) = (A2*A1, A2*B1+B2)
    for (int off = 1; off < NTHR; off <<= 1) {
        float a1 = 1.0f, b1 = 0.0f;
        const float a2 = sA[tid];
        const float b2 = sB[tid];
        if (tid >= off) { a1 = sA[tid - off]; b1 = sB[tid - off]; }
        __syncthreads();
        if (tid >= off) { sA[tid] = a2 * a1; sB[tid] = fmaf(a2, b1, b2); }
        __syncthreads();
    }

    // pass 2: re-sweep chunk with true carry-in; build transient
    {
        float y = (tid == 0) ? 0.0f : sB[tid - 1];
        const int start = tid * CHUNK;
        const int end   = min(start + CHUNK, NSAMP);
        for (int k = start; k < end; ++k) {
            float x = noise_t[k];
            y = CUTOFF * x + (1.0f - CUTOFF) * y;          // filtered noise
            float tt = (float)k * tstep;
            float s  = sinf(6.2831855f * freq_t * tt) * __expf(-decay_t * tt) * gain_t;
            s = tanhf(s * sat);
            float nc = y * __expf(-(decay_t * 20.0f) * tt) * (gain_t * 0.5f);
            trans[k] = s + nc;
        }
    }
    __syncthreads();

    // ======== Phase 2: resonator recurrence ========
    const float D  = 48000.0f / freq_r;
    const int   Di = (int)D;

    const bool fast = (D >= 1.0f) && ((float)Di == D) && (Di <= NTHR);
    if (fast) {
        // Integer delay: frac == 0 exactly -> D independent chains, no barriers.
        if (tid < Di) {
            float y = trans[tid];      // i < D  =>  valid==0  =>  out = transient
            res[tid] = y;
            for (int i = tid + Di; i < NSAMP; i += Di) {
                y = fmaf(feedback, y, trans[i]);
                res[i] = y;
            }
        }
        __syncthreads();
    } else {
        // Generic fractional delay: wave-synchronous, wave width W < ceil(D)
        int cD = (int)ceilf(D);
        int W  = max(cD - 1, 1);
        W = min(W, NTHR);
        for (int s0 = 1; s0 < NSAMP; s0 += W) {
            const int i = s0 + tid;
            if (tid < W && i < NSAMP) {
                float delayed = (float)i - D;
                float valid   = (delayed >= 0.0f) ? 1.0f : 0.0f;
                int fl = (int)floorf(delayed);
                fl = min(max(fl, 0), NSAMP - 1);
                int ce = min(fl + 1, NSAMP - 1);
                float frac = delayed - (float)fl;          // after clamp, as in reference
                float interp = (1.0f - frac) * res[fl] + frac * res[ce];
                res[i] = trans[i] + feedback * interp * valid;
            }
            __syncthreads();
        }
    }

    // ======== Phase 3: noise generator + final sum ========
    for (int i = tid; i < NSAMP; i += NTHR) {
        float tt  = (float)i * tstep;
        float env = (1.0f - __expf(-attack_n * tt)) * __expf(-decay_n * tt);
        out[i] = trans[i] + noise_n[i] * env * gain_n + res[i] * gain_r;
    }
}

extern "C" void kernel_launch(void* const* d_in, const int* in_sizes, int n_in,
                              void* d_out, int out_size)
{
    const float* params  = (const float*)d_in[0];
    const float* noise_t = (const float*)d_in[1];
    const float* noise_n = (const float*)d_in[2];
    float* out = (float*)d_out;

    const size_t smem_bytes = 2u * NSAMP * sizeof(float);   // 192000 B
    cudaFuncSetAttribute(drum_synth_kernel,
                         cudaFuncAttributeMaxDynamicSharedMemorySize,
                         (int)smem_bytes);

    drum_synth_kernel<<<1, NTHR, smem_bytes>>>(params, noise_t, noise_n, out);
}

// round 2
// speedup vs baseline: 1.6654x; 1.6654x over previous
#include <cuda_runtime.h>
#include <math.h>

#define NSAMP 24000
#define NTHR  1024
#define CHUNK 24            // 1000 threads * 24 = 24000 exactly
#define NWARP 32
#define CUTOFF 0.1f
#define OMC    0.9f         // 1 - CUTOFF

__device__ __forceinline__ float tanh_fast(float x) {
    // exact identity tanh(x) = 1 - 2/(e^{2x}+1); saturates correctly at +-inf
    float e = __expf(2.0f * x);
    return 1.0f - __fdividef(2.0f, e + 1.0f);
}

__global__ __launch_bounds__(NTHR, 1)
void drum_synth_kernel(const float* __restrict__ p,
                       const float* __restrict__ noise_t,
                       const float* __restrict__ noise_n,
                       float* __restrict__ out)
{
    extern __shared__ float smem[];
    float* trans = smem;            // NSAMP floats
    float* res   = smem + NSAMP;    // NSAMP floats
    __shared__ float sA[NWARP];
    __shared__ float sB[NWARP];

    const int tid  = threadIdx.x;
    const int lane = tid & 31;
    const int wid  = tid >> 5;

    const float decay_t  = p[1];
    const float freq_t   = p[2];
    const float sat      = p[3];
    const float gain_t   = p[4];
    const float freq_r   = p[5];
    const float feedback = p[6];
    const float gain_r   = p[7];
    const float attack_n = p[8];
    const float decay_n  = p[9];
    const float gain_n   = p[10];

    const float tstep = 1.0f / 23999.0f;

    const int  start  = tid * CHUNK;
    const bool active = (start < NSAMP);   // threads 0..999

    // ======== Phase 1a: per-chunk affine reduce of one-pole filter ========
    // Starting from y=0: after chunk, y -> a*y0 + b with a = 0.9^24
    float a = 1.0f, b = 0.0f;
    if (active) {
        #pragma unroll
        for (int k = 0; k < CHUNK; ++k) {
            float x = noise_t[start + k];
            b = fmaf(OMC, b, CUTOFF * x);
        }
        // 0.9^24, branch-free constant chain
        a = OMC;
        #pragma unroll
        for (int q = 0; q < 4; ++q) a *= a;   // 0.9^16
        a *= OMC * OMC;                        // 0.9^18
        a *= OMC * OMC * OMC;                  // 0.9^21
        a *= OMC * OMC * OMC;                  // 0.9^24
    }

    // ======== Phase 1b: warp-shuffle affine scan ========
    #pragma unroll
    for (int off = 1; off < 32; off <<= 1) {
        float au = __shfl_up_sync(0xffffffffu, a, off);
        float bu = __shfl_up_sync(0xffffffffu, b, off);
        if (lane >= off) { b = fmaf(a, bu, b); a *= au; }
    }
    // intra-warp exclusive
    float a_ie = __shfl_up_sync(0xffffffffu, a, 1);
    float b_ie = __shfl_up_sync(0xffffffffu, b, 1);
    if (lane == 0) { a_ie = 1.0f; b_ie = 0.0f; }
    if (lane == 31) { sA[wid] = a; sB[wid] = b; }
    __syncthreads();
    if (wid == 0) {
        float wa = sA[lane], wb = sB[lane];
        #pragma unroll
        for (int off = 1; off < 32; off <<= 1) {
            float au = __shfl_up_sync(0xffffffffu, wa, off);
            float bu = __shfl_up_sync(0xffffffffu, wb, off);
            if (lane >= off) { wb = fmaf(wa, bu, wb); wa *= au; }
        }
        sA[lane] = wa; sB[lane] = wb;
    }
    __syncthreads();
    const float b_wp = (wid == 0) ? 0.0f : sB[wid - 1];
    float y = fmaf(a_ie, b_wp, b_ie);   // carry-in filter state for this chunk

    // ======== Phase 2: transient via recurrences (no per-sample transcendentals) ========
    if (active) {
        const float t0 = (float)start * tstep;
        const float w  = 6.2831853f * freq_t;
        float sn, cs, sd, cd;
        sincosf(w * t0,    &sn, &cs);
        sincosf(w * tstep, &sd, &cd);
        float e1 = __expf(-decay_t * t0);
        float m1 = __expf(-decay_t * tstep);
        float e2 = __expf(-20.0f * decay_t * t0);
        float m2 = __expf(-20.0f * decay_t * tstep);
        const float g2 = gain_t * 0.5f;

        #pragma unroll 4
        for (int k = 0; k < CHUNK; ++k) {
            float x = noise_t[start + k];
            y = fmaf(OMC, y, CUTOFF * x);                  // one-pole
            float sv = sn * e1 * gain_t;                    // sine * decay * gain
            float sq = tanh_fast(sv * sat);                 // saturation
            float nc = y * e2 * g2;                         // filtered-noise component
            trans[start + k] = sq + nc;
            float sn2 = fmaf(sn, cd,  cs * sd);             // rotate phase
            float cs2 = fmaf(cs, cd, -sn * sd);
            sn = sn2; cs = cs2;
            e1 *= m1; e2 *= m2;                             // advance decays
        }
    }
    __syncthreads();

    // ======== Phase 3: resonator recurrence ========
    const float D  = 48000.0f / freq_r;
    const int   Di = (int)D;
    const bool fast = (D >= 1.0f) && ((float)Di == D) && (Di <= NTHR);

    if (fast) {
        // Integer delay: frac == 0 exactly -> Di independent chains, no barriers.
        if (tid < Di) {
            float yv = trans[tid];      // i < D => valid==0 => out = transient
            res[tid] = yv;
            #pragma unroll 4
            for (int i = tid + Di; i < NSAMP; i += Di) {
                yv = fmaf(feedback, yv, trans[i]);
                res[i] = yv;
            }
        }
        __syncthreads();
    } else {
        // Generic fractional delay: wave-synchronous, wave width W <= ceil(D)-1
        if (tid == 0) res[0] = trans[0];
        int cD = (int)ceilf(D);
        int W  = min(max(cD - 1, 1), NTHR);
        __syncthreads();
        for (int s0 = 1; s0 < NSAMP; s0 += W) {
            const int i = s0 + tid;
            if (tid < W && i < NSAMP) {
                float delayed = (float)i - D;
                float valid   = (delayed >= 0.0f) ? 1.0f : 0.0f;
                int fl = min(max((int)floorf(delayed), 0), NSAMP - 1);
                int ce = min(fl + 1, NSAMP - 1);
                float frac = delayed - (float)fl;          // after clamp, as in reference
                float interp = (1.0f - frac) * res[fl] + frac * res[ce];
                res[i] = trans[i] + feedback * interp * valid;
            }
            __syncthreads();
        }
    }

    // ======== Phase 4: noise envelope (recurrence) + final sum ========
    {
        const float tt0 = (float)tid * tstep;
        const float dT  = (float)NTHR * tstep;
        float eA = __expf(-attack_n * tt0);
        float mA = __expf(-attack_n * dT);
        float eD = __expf(-decay_n * tt0);
        float mD = __expf(-decay_n * dT);
        for (int i = tid; i < NSAMP; i += NTHR) {
            float env = (1.0f - eA) * eD;
            out[i] = fmaf(noise_n[i] * gain_n, env, fmaf(res[i], gain_r, trans[i]));
            eA *= mA; eD *= mD;
        }
    }
}

extern "C" void kernel_launch(void* const* d_in, const int* in_sizes, int n_in,
                              void* d_out, int out_size)
{
    const float* params  = (const float*)d_in[0];
    const float* noise_t = (const float*)d_in[1];
    const float* noise_n = (const float*)d_in[2];
    float* out = (float*)d_out;

    const size_t smem_bytes = 2u * NSAMP * sizeof(float);   // 192000 B
    cudaFuncSetAttribute(drum_synth_kernel,
                         cudaFuncAttributeMaxDynamicSharedMemorySize,
                         (int)smem_bytes);

    drum_synth_kernel<<<1, NTHR, smem_bytes>>>(params, noise_t, noise_n, out);
}

// round 3
// speedup vs baseline: 2.8103x; 1.6875x over previous
#include <cuda_runtime.h>
#include <math.h>

#define NSAMP 24000
#define NV4   6000          // NSAMP / 4
#define NTHR  1024
#define CHUNK 24            // 1000 threads * 24 = 24000 exactly
#define NWARP 32
#define CUTOFF 0.1f
#define OMC    0.9f         // 1 - CUTOFF
#define A24    0.07976644307687256f   // 0.9^24

__device__ __forceinline__ float tanh_fast(float x) {
    // exact identity tanh(x) = 1 - 2/(e^{2x}+1); saturates correctly at +-inf
    float e = __expf(2.0f * x);
    return 1.0f - __fdividef(2.0f, e + 1.0f);
}

__global__ __launch_bounds__(NTHR, 1)
void drum_synth_kernel(const float* __restrict__ p,
                       const float* __restrict__ noise_t,
                       const float* __restrict__ noise_n,
                       float* __restrict__ out)
{
    extern __shared__ float smem[];
    float*  trans  = smem;                       // NSAMP floats
    float4* transv = (float4*)smem;
    float*  res    = smem + NSAMP;               // NSAMP floats (scratch, then resonator)
    float4* resv   = (float4*)(smem + NSAMP);
    __shared__ float sA[NWARP];
    __shared__ float sB[NWARP];

    const int tid  = threadIdx.x;
    const int lane = tid & 31;
    const int wid  = tid >> 5;

    const float decay_t  = p[1];
    const float freq_t   = p[2];
    const float sat      = p[3];
    const float gain_t   = p[4];
    const float freq_r   = p[5];
    const float feedback = p[6];
    const float gain_r   = p[7];
    const float attack_n = p[8];
    const float decay_n  = p[9];
    const float gain_n   = p[10];

    const float tstep = 1.0f / 23999.0f;

    // ======== Phase 0: coalesced float4 load of noise_t into res[] scratch ========
    {
        const float4* ntv = (const float4*)noise_t;
        #pragma unroll
        for (int j = 0; j < 6; ++j) {
            int i4 = tid + j * NTHR;
            if (i4 < NV4) resv[i4] = ntv[i4];
        }
    }
    __syncthreads();

    const bool active = (tid < 1000);
    const int  v0     = tid * 6;                 // chunk start in float4 units

    // ======== Phase 1a: per-chunk filter partials (y starting from 0) ========
    // Stores b_k (partial filter output) back into res[] in place.
    float a = active ? A24 : 1.0f;               // 0.9^24 chunk multiplier
    float b = 0.0f;
    if (active) {
        #pragma unroll
        for (int j = 0; j < 6; ++j) {
            float4 x = resv[v0 + j];
            float b0 = fmaf(OMC, b,  CUTOFF * x.x);
            float b1 = fmaf(OMC, b0, CUTOFF * x.y);
            float b2 = fmaf(OMC, b1, CUTOFF * x.z);
            float b3 = fmaf(OMC, b2, CUTOFF * x.w);
            resv[v0 + j] = make_float4(b0, b1, b2, b3);
            b = b3;
        }
    }

    // ======== Phase 1b: warp-shuffle affine scan for carry-in ========
    #pragma unroll
    for (int off = 1; off < 32; off <<= 1) {
        float au = __shfl_up_sync(0xffffffffu, a, off);
        float bu = __shfl_up_sync(0xffffffffu, b, off);
        if (lane >= off) { b = fmaf(a, bu, b); a *= au; }
    }
    float a_ie = __shfl_up_sync(0xffffffffu, a, 1);
    float b_ie = __shfl_up_sync(0xffffffffu, b, 1);
    if (lane == 0)  { a_ie = 1.0f; b_ie = 0.0f; }
    if (lane == 31) { sA[wid] = a; sB[wid] = b; }
    __syncthreads();
    if (wid == 0) {
        float wa = sA[lane], wb = sB[lane];
        #pragma unroll
        for (int off = 1; off < 32; off <<= 1) {
            float au = __shfl_up_sync(0xffffffffu, wa, off);
            float bu = __shfl_up_sync(0xffffffffu, wb, off);
            if (lane >= off) { wb = fmaf(wa, bu, wb); wa *= au; }
        }
        sA[lane] = wa; sB[lane] = wb;
    }
    __syncthreads();
    const float b_wp = (wid == 0) ? 0.0f : sB[wid - 1];
    const float y_in = fmaf(a_ie, b_wp, b_ie);   // filter state entering this chunk

    // ======== Phase 2: transient via recurrences, zero global loads ========
    if (active) {
        const float t0 = (float)(tid * CHUNK) * tstep;
        const float w  = 6.2831853f * freq_t;
        float sn, cs;
        sincosf(w * t0, &sn, &cs);               // accurate for large start phase
        const float sd = __sinf(w * tstep);      // tiny arg: fast versions exact enough
        const float cd = __cosf(w * tstep);
        float e1 = __expf(-decay_t * t0);
        const float m1 = __expf(-decay_t * tstep);
        float e2 = __expf(-20.0f * decay_t * t0);
        const float m2 = __expf(-20.0f * decay_t * tstep);
        const float g2  = gain_t * 0.5f;
        const float gts = gain_t * sat;
        float ck = OMC;                          // 0.9^(k+1)

        #pragma unroll
        for (int j = 0; j < 6; ++j) {
            float4 b4 = resv[v0 + j];
            float bk[4] = {b4.x, b4.y, b4.z, b4.w};
            float tr[4];
            #pragma unroll
            for (int q = 0; q < 4; ++q) {
                float y = fmaf(ck, y_in, bk[q]);           // exact filter output
                ck *= OMC;
                float s = tanh_fast(sn * e1 * gts);        // saturated sine
                tr[q] = fmaf(y * e2, g2, s);               // + noise component
                float sn2 = fmaf(sn, cd,  cs * sd);        // rotate phase
                float cs2 = fmaf(cs, cd, -sn * sd);
                sn = sn2; cs = cs2;
                e1 *= m1; e2 *= m2;
            }
            transv[v0 + j] = make_float4(tr[0], tr[1], tr[2], tr[3]);
        }
    }

    // ======== Phase 4 setup (params-only, hoisted to overlap resonator) ========
    const float tt0   = (float)(4 * tid) * tstep;
    const float stepT = 4096.0f * tstep;
    float eA = __expf(-attack_n * tt0);
    float eD = __expf(-decay_n  * tt0);
    const float mA = __expf(-attack_n * stepT);
    const float mD = __expf(-decay_n  * stepT);
    const float a1 = __expf(-attack_n * tstep);
    const float d1 = __expf(-decay_n  * tstep);
    const float a2 = a1 * a1, a3 = a2 * a1;
    const float d2 = d1 * d1, d3 = d2 * d1;

    __syncthreads();   // trans[] complete

    // ======== Phase 3: resonator recurrence (res[] scratch fully overwritten) ========
    const float D  = 48000.0f / freq_r;
    const int   Di = (int)D;
    const bool fast = (D >= 1.0f) && ((float)Di == D) && (Di <= NTHR);

    if (fast) {
        // Integer delay: frac == 0 exactly -> Di independent chains, register-resident.
        if (tid < Di) {
            float yv = trans[tid];       // i < D => valid==0 => out = transient
            res[tid] = yv;
            #pragma unroll 2
            for (int i = tid + Di; i < NSAMP; i += Di) {
                yv = fmaf(feedback, yv, trans[i]);
                res[i] = yv;
            }
        }
        __syncthreads();
    } else {
        // Generic fractional delay: wave-synchronous. Zero res first (reference
        // scans over a zero-initialized array; needed when ce can reach i).
        for (int i = tid; i < NSAMP; i += NTHR) res[i] = 0.0f;
        __syncthreads();
        if (tid == 0) res[0] = trans[0];
        int cD = (int)ceilf(D);
        int W  = min(max(cD - 1, 1), NTHR);
        __syncthreads();
        for (int s0 = 1; s0 < NSAMP; s0 += W) {
            const int i = s0 + tid;
            if (tid < W && i < NSAMP) {
                float delayed = (float)i - D;
                float valid   = (delayed >= 0.0f) ? 1.0f : 0.0f;
                int fl = min(max((int)floorf(delayed), 0), NSAMP - 1);
                int ce = min(fl + 1, NSAMP - 1);
                float frac = delayed - (float)fl;      // after clamp, as in reference
                float interp = (1.0f - frac) * res[fl] + frac * res[ce];
                res[i] = trans[i] + feedback * interp * valid;
            }
            __syncthreads();
        }
    }

    // ======== Phase 4: noise envelope (recurrence) + final sum, fully vectorized ========
    {
        const float4* nnv  = (const float4*)noise_n;
        float4*       outv = (float4*)out;
        #pragma unroll
        for (int j = 0; j < 6; ++j) {
            int i4 = tid + j * NTHR;
            if (i4 < NV4) {
                float4 nn = nnv[i4];
                float4 tr = transv[i4];
                float4 rs = resv[i4];
                float e0v = (1.0f - eA)      *  eD;
                float e1v = (1.0f - eA * a1) * (eD * d1);
                float e2v = (1.0f - eA * a2) * (eD * d2);
                float e3v = (1.0f - eA * a3) * (eD * d3);
                float4 o;
                o.x = fmaf(nn.x * gain_n, e0v, fmaf(rs.x, gain_r, tr.x));
                o.y = fmaf(nn.y * gain_n, e1v, fmaf(rs.y, gain_r, tr.y));
                o.z = fmaf(nn.z * gain_n, e2v, fmaf(rs.z, gain_r, tr.z));
                o.w = fmaf(nn.w * gain_n, e3v, fmaf(rs.w, gain_r, tr.w));
                outv[i4] = o;
            }
            eA *= mA; eD *= mD;
        }
    }
}

extern "C" void kernel_launch(void* const* d_in, const int* in_sizes, int n_in,
                              void* d_out, int out_size)
{
    const float* params  = (const float*)d_in[0];
    const float* noise_t = (const float*)d_in[1];
    const float* noise_n = (const float*)d_in[2];
    float* out = (float*)d_out;

    const size_t smem_bytes = 2u * NSAMP * sizeof(float);   // 192000 B
    cudaFuncSetAttribute(drum_synth_kernel,
                         cudaFuncAttributeMaxDynamicSharedMemorySize,
                         (int)smem_bytes);

    drum_synth_kernel<<<1, NTHR, smem_bytes>>>(params, noise_t, noise_n, out);
}

// round 4
// speedup vs baseline: 2.8164x; 1.0022x over previous
#include <cuda_runtime.h>
#include <math.h>

#define NSAMP 24000
#define NV4   6000            // NSAMP / 4
#define NTHR  1024
#define CHUNK 24              // 1000 chunks * 24 = 24000 exactly
#define NCHUNK 1000
#define ROWV4 7               // padded chunk row: 7 float4 = 28 words (24 used)
#define NWARP 32
#define CUTOFF 0.1f
#define OMC    0.9f           // 1 - CUTOFF
#define A24    0.07976644307687256f   // 0.9^24

// smem layout (floats):
//   [0            .. 24000)   trans  (sample order)
//   [24000        .. 52000)   scratch (padded chunks: chunk c at 28*c), later res overlays
//   [52000        .. 53000)   sYin (per-chunk filter carry-in)
//   [53024        .. 53056)   powOMC table (0.9^{k+1})
#define OFF_SCRATCH 24000
#define OFF_YIN     52000
#define OFF_POW     53024
#define SMEM_FLOATS 53056

__device__ __forceinline__ float tanh_fast(float x) {
    // exact identity tanh(x) = 1 - 2/(e^{2x}+1); saturates correctly at +-inf
    float e = __expf(2.0f * x);
    return 1.0f - __fdividef(2.0f, e + 1.0f);
}

__global__ __launch_bounds__(NTHR, 1)
void drum_synth_kernel(const float* __restrict__ p,
                       const float* __restrict__ noise_t,
                       const float* __restrict__ noise_n,
                       float* __restrict__ out)
{
    extern __shared__ float smem[];
    float*  trans    = smem;
    float4* transv   = (float4*)smem;
    float*  scratch  = smem + OFF_SCRATCH;
    float4* scratchv = (float4*)(smem + OFF_SCRATCH);
    float*  res      = smem + OFF_SCRATCH;          // overlays scratch (dead by then)
    float4* resv     = (float4*)(smem + OFF_SCRATCH);
    float*  sYin     = smem + OFF_YIN;
    float*  powTab   = smem + OFF_POW;
    __shared__ float sA[NWARP];
    __shared__ float sB[NWARP];

    const int tid  = threadIdx.x;
    const int lane = tid & 31;
    const int wid  = tid >> 5;

    const float decay_t  = p[1];
    const float freq_t   = p[2];
    const float sat      = p[3];
    const float gain_t   = p[4];
    const float freq_r   = p[5];
    const float feedback = p[6];
    const float gain_r   = p[7];
    const float attack_n = p[8];
    const float decay_n  = p[9];
    const float gain_n   = p[10];

    const float tstep = 1.0f / 23999.0f;

    // ======== Phase 0: stage noise_t into padded-chunk scratch (coalesced) ========
    {
        const float4* ntv = (const float4*)noise_t;
        #pragma unroll
        for (int j = 0; j < 6; ++j) {
            int i4 = tid + j * NTHR;
            if (i4 < NV4) {
                int c = i4 / 6;                     // chunk (6 quads per chunk)
                scratchv[c * ROWV4 + (i4 - 6 * c)] = ntv[i4];
            }
        }
        if (tid == 1023) {                          // spare thread builds 0.9^{k+1} table
            float pw = 1.0f;
            #pragma unroll
            for (int k = 0; k < CHUNK; ++k) { pw *= OMC; powTab[k] = pw; }
        }
    }

    // ---- phase-4 envelope setup (params only; hoisted for overlap) ----
    const float tt0   = (float)(4 * tid) * tstep;
    const float stepT = 4096.0f * tstep;
    float eA = __expf(-attack_n * tt0);
    float eD = __expf(-decay_n  * tt0);
    const float mAq = __expf(-attack_n * stepT);
    const float mDq = __expf(-decay_n  * stepT);
    const float a1 = __expf(-attack_n * tstep);
    const float d1 = __expf(-decay_n  * tstep);
    const float a2 = a1 * a1, a3 = a2 * a1;
    const float d2 = d1 * d1, d3 = d2 * d1;

    __syncthreads();

    const bool active = (tid < NCHUNK);

    // ======== Phase 1a: per-chunk filter partials (y from 0), in-place ========
    float a = active ? A24 : 1.0f;
    float b = 0.0f;
    if (active) {
        const int base = tid * ROWV4;
        #pragma unroll
        for (int j = 0; j < 6; ++j) {
            float4 x = scratchv[base + j];
            float b0 = fmaf(OMC, b,  CUTOFF * x.x);
            float b1 = fmaf(OMC, b0, CUTOFF * x.y);
            float b2 = fmaf(OMC, b1, CUTOFF * x.z);
            float b3 = fmaf(OMC, b2, CUTOFF * x.w);
            scratchv[base + j] = make_float4(b0, b1, b2, b3);
            b = b3;
        }
    }

    // ======== Phase 1b: warp-shuffle affine scan -> per-chunk carry-in ========
    #pragma unroll
    for (int off = 1; off < 32; off <<= 1) {
        float au = __shfl_up_sync(0xffffffffu, a, off);
        float bu = __shfl_up_sync(0xffffffffu, b, off);
        if (lane >= off) { b = fmaf(a, bu, b); a *= au; }
    }
    float a_ie = __shfl_up_sync(0xffffffffu, a, 1);
    float b_ie = __shfl_up_sync(0xffffffffu, b, 1);
    if (lane == 0)  { a_ie = 1.0f; b_ie = 0.0f; }
    if (lane == 31) { sA[wid] = a; sB[wid] = b; }
    __syncthreads();
    if (wid == 0) {
        float wa = sA[lane], wb = sB[lane];
        #pragma unroll
        for (int off = 1; off < 32; off <<= 1) {
            float au = __shfl_up_sync(0xffffffffu, wa, off);
            float bu = __shfl_up_sync(0xffffffffu, wb, off);
            if (lane >= off) { wb = fmaf(wa, bu, wb); wa *= au; }
        }
        sA[lane] = wa; sB[lane] = wb;
    }
    __syncthreads();
    {
        const float b_wp = (wid == 0) ? 0.0f : sB[wid - 1];
        if (active) sYin[tid] = fmaf(a_ie, b_wp, b_ie);   // filter state entering chunk
    }
    __syncthreads();   // partials + sYin + powTab visible to everyone

    // ======== Phase 2: transient, STRIDED float4 quads (conflict-free) ========
    {
        const float w = 6.2831853f * freq_t;
        float snq, csq;
        sincosf(w * (float)(4 * tid) * tstep, &snq, &csq);   // quad start phase
        const float sd = __sinf(w * tstep);                   // per-sample rotation
        const float cd = __cosf(w * tstep);
        float SDv, CDv;
        sincosf(w * stepT, &SDv, &CDv);                       // per-4096-sample rotation
        float E1 = __expf(-decay_t * (float)(4 * tid) * tstep);
        float E2 = __expf(-20.0f * decay_t * (float)(4 * tid) * tstep);
        const float m1 = __expf(-decay_t * tstep);
        const float m2 = __expf(-20.0f * decay_t * tstep);
        const float M1 = __expf(-decay_t * stepT);
        const float M2 = __expf(-20.0f * decay_t * stepT);
        const float g2  = gain_t * 0.5f;
        const float gts = gain_t * sat;

        #pragma unroll
        for (int j = 0; j < 6; ++j) {
            int i4 = tid + j * NTHR;
            if (i4 < NV4) {
                int c = i4 / 6;                 // = (4*i4)/24 exactly (4 | 24)
                int q = i4 - 6 * c;             // quad within chunk
                int k = 4 * q;                  // sample offset in chunk
                float4 b4 = scratchv[c * ROWV4 + q];
                float yin = sYin[c];
                float ck  = powTab[k];          // 0.9^{k+1}
                float sn = snq, cs = csq, e1 = E1, e2 = E2;
                float bk[4] = {b4.x, b4.y, b4.z, b4.w};
                float tr[4];
                #pragma unroll
                for (int s = 0; s < 4; ++s) {
                    float y  = fmaf(ck, yin, bk[s]);            // exact filter output
                    float sq = tanh_fast(sn * e1 * gts);        // saturated sine
                    tr[s] = fmaf(y * e2, g2, sq);               // + noise component
                    float sn2 = fmaf(sn, cd,  cs * sd);
                    float cs2 = fmaf(cs, cd, -sn * sd);
                    sn = sn2; cs = cs2;
                    e1 *= m1; e2 *= m2; ck *= OMC;
                }
                transv[i4] = make_float4(tr[0], tr[1], tr[2], tr[3]);
            }
            // advance quad state by 4096 samples (unconditional)
            float sn2 = fmaf(snq, CDv,  csq * SDv);
            float cs2 = fmaf(csq, CDv, -snq * SDv);
            snq = sn2; csq = cs2;
            E1 *= M1; E2 *= M2;
        }
    }
    __syncthreads();   // trans[] complete; scratch now dead -> res overlays it

    // ======== Phase 3: resonator recurrence ========
    const float D  = 48000.0f / freq_r;
    const int   Di = (int)D;
    const bool fastp = (D >= 1.0f) && ((float)Di == D) && (Di <= NTHR);

    if (fastp) {
        // Integer delay: frac == 0 exactly -> Di independent register chains.
        if (tid < Di) {
            float yv = trans[tid];       // i < D => valid==0 => out = transient
            res[tid] = yv;
            #pragma unroll 2
            for (int i = tid + Di; i < NSAMP; i += Di) {
                yv = fmaf(feedback, yv, trans[i]);
                res[i] = yv;
            }
        }
        __syncthreads();
    } else {
        // Generic fractional delay: wave-synchronous over zeroed res.
        for (int i = tid; i < NSAMP; i += NTHR) res[i] = 0.0f;
        __syncthreads();
        if (tid == 0) res[0] = trans[0];
        int cD = (int)ceilf(D);
        int W  = min(max(cD - 1, 1), NTHR);
        __syncthreads();
        for (int s0 = 1; s0 < NSAMP; s0 += W) {
            const int i = s0 + tid;
            if (tid < W && i < NSAMP) {
                float delayed = (float)i - D;
                float valid   = (delayed >= 0.0f) ? 1.0f : 0.0f;
                int fl = min(max((int)floorf(delayed), 0), NSAMP - 1);
                int ce = min(fl + 1, NSAMP - 1);
                float frac = delayed - (float)fl;      // after clamp, as in reference
                float interp = (1.0f - frac) * res[fl] + frac * res[ce];
                res[i] = trans[i] + feedback * interp * valid;
            }
            __syncthreads();
        }
    }

    // ======== Phase 4: noise envelope (recurrence) + final sum, vectorized ========
    {
        const float4* nnv  = (const float4*)noise_n;
        float4*       outv = (float4*)out;
        #pragma unroll
        for (int j = 0; j < 6; ++j) {
            int i4 = tid + j * NTHR;
            if (i4 < NV4) {
                float4 nn = nnv[i4];
                float4 tr = transv[i4];
                float4 rs = resv[i4];
                float e0v = (1.0f - eA)      *  eD;
                float e1v = (1.0f - eA * a1) * (eD * d1);
                float e2v = (1.0f - eA * a2) * (eD * d2);
                float e3v = (1.0f - eA * a3) * (eD * d3);
                float4 o;
                o.x = fmaf(nn.x * gain_n, e0v, fmaf(rs.x, gain_r, tr.x));
                o.y = fmaf(nn.y * gain_n, e1v, fmaf(rs.y, gain_r, tr.y));
                o.z = fmaf(nn.z * gain_n, e2v, fmaf(rs.z, gain_r, tr.z));
                o.w = fmaf(nn.w * gain_n, e3v, fmaf(rs.w, gain_r, tr.w));
                outv[i4] = o;
            }
            eA *= mAq; eD *= mDq;
        }
    }
}

extern "C" void kernel_launch(void* const* d_in, const int* in_sizes, int n_in,
                              void* d_out, int out_size)
{
    const float* params  = (const float*)d_in[0];
    const float* noise_t = (const float*)d_in[1];
    const float* noise_n = (const float*)d_in[2];
    float* out = (float*)d_out;

    const size_t smem_bytes = SMEM_FLOATS * sizeof(float);   // 212224 B
    cudaFuncSetAttribute(drum_synth_kernel,
                         cudaFuncAttributeMaxDynamicSharedMemorySize,
                         (int)smem_bytes);

    drum_synth_kernel<<<1, NTHR, smem_bytes>>>(params, noise_t, noise_n, out);
}